// round 4
// baseline (speedup 1.0000x reference)
#include <cuda_runtime.h>
#include <math.h>

// Problem constants
constexpr int B_   = 16;
constexpr int H_   = 16;
constexpr int HD_  = 128;
constexpr int D_   = 2048;
constexpr int SPAST = 4096;
constexpr int SPLITS = 8;
constexpr int CHUNK  = 512;   // SPAST / SPLITS
constexpr float SCALING = 0.08838834764831845f;  // 128^-0.5

// Scratch (static device globals — no allocation allowed)
__device__ float g_q[B_ * D_];
__device__ float g_attn[B_ * D_];
__device__ float g_pm[B_ * H_ * SPLITS];
__device__ float g_pl[B_ * H_ * SPLITS];
__device__ float g_pacc[B_ * H_ * SPLITS * HD_];
__device__ unsigned int g_cnt[B_ * H_];   // zero-initialized; reset by last block

struct GemvArgs {
    const float* W[3];
    float*       out[3];
    float        scale[3];
};

// ---------------------------------------------------------------------------
// Single init: seed q/knew/vnew/out with their biases so the split-K gemvs
// can pure-atomicAdd. out is untouched until the Wo gemv, so seeding it here
// is safe and saves a kernel launch.
// ---------------------------------------------------------------------------
__global__ __launch_bounds__(256) void init_kernel(
    float* q, float* knew, float* vnew, float* out,
    const float* __restrict__ bq, const float* __restrict__ bk,
    const float* __restrict__ bv, const float* __restrict__ bo) {
    int idx = blockIdx.x * 256 + threadIdx.x;   // [0, 32768)
    int o = idx & (D_ - 1);
    q[idx]    = bq[o] * SCALING;
    knew[idx] = bk[o];
    vnew[idx] = bv[o];
    out[idx]  = bo[o];
}

// ---------------------------------------------------------------------------
// Split-K GEMV: out[b, o] += scale * sum_{d in chunk} x[b,d] * W[o,d]
// Each warp owns 4 consecutive output rows, register-blocks all 16 batches,
// and covers a 2048/KSPLIT slice of the reduction dim (gridDim.y = KSPLIT).
// ---------------------------------------------------------------------------
template <int KSPLIT>
__global__ __launch_bounds__(256) void gemv_kernel(const float* __restrict__ x,
                                                   GemvArgs a) {
    int gw   = (blockIdx.x * 256 + threadIdx.x) >> 5;
    int lane = threadIdx.x & 31;
    int row0 = gw * 4;
    int mi   = row0 >> 11;      // which matrix (rows are 2048 per matrix)
    int o0   = row0 & 2047;

    const float4* W = (const float4*)a.W[mi];
    const float4* X = (const float4*)x;

    float acc[4][16];
#pragma unroll
    for (int r = 0; r < 4; r++)
#pragma unroll
        for (int b = 0; b < 16; b++) acc[r][b] = 0.f;

    constexpr int ITERS = 16 / KSPLIT;
    int i0 = blockIdx.y * ITERS;

#pragma unroll 2
    for (int ii = 0; ii < ITERS; ii++) {
        int d4 = (i0 + ii) * 32 + lane;          // float4 index into a row
        float4 w0 = W[(size_t)(o0 + 0) * 512 + d4];
        float4 w1 = W[(size_t)(o0 + 1) * 512 + d4];
        float4 w2 = W[(size_t)(o0 + 2) * 512 + d4];
        float4 w3 = W[(size_t)(o0 + 3) * 512 + d4];
#pragma unroll
        for (int b = 0; b < 16; b++) {
            float4 xv = X[b * 512 + d4];
            acc[0][b] += w0.x * xv.x + w0.y * xv.y + w0.z * xv.z + w0.w * xv.w;
            acc[1][b] += w1.x * xv.x + w1.y * xv.y + w1.z * xv.z + w1.w * xv.w;
            acc[2][b] += w2.x * xv.x + w2.y * xv.y + w2.z * xv.z + w2.w * xv.w;
            acc[3][b] += w3.x * xv.x + w3.y * xv.y + w3.z * xv.z + w3.w * xv.w;
        }
    }

    // Warp-reduce each of the 64 partial sums
#pragma unroll
    for (int r = 0; r < 4; r++)
#pragma unroll
        for (int b = 0; b < 16; b++) {
            float v = acc[r][b];
            v += __shfl_xor_sync(0xffffffffu, v, 16);
            v += __shfl_xor_sync(0xffffffffu, v, 8);
            v += __shfl_xor_sync(0xffffffffu, v, 4);
            v += __shfl_xor_sync(0xffffffffu, v, 2);
            v += __shfl_xor_sync(0xffffffffu, v, 1);
            acc[r][b] = v;
        }

    float* out = a.out[mi];
    float  sc  = a.scale[mi];
#pragma unroll
    for (int r = 0; r < 4; r++)
#pragma unroll
        for (int b = 0; b < 16; b++)
            if (lane == b)
                atomicAdd(&out[b * D_ + o0 + r], acc[r][b] * sc);
}

// ---------------------------------------------------------------------------
// Split-S flash-decode attention with fused combine.
// grid = (256 bh, 8 splits), block = 256 (8 warps). Warp-per-row online
// softmax; each lane owns 4 contiguous head-dim elements (float4).
// K/V are a 1 GB single-use stream: __ldcs keeps them out of L2's way.
// The last block per bh (atomic ticket) combines the 8 split partials.
// ---------------------------------------------------------------------------
__global__ __launch_bounds__(256) void attn_partial_kernel(
    const float* __restrict__ pk, const float* __restrict__ pv,
    const float* __restrict__ mask,
    const float* __restrict__ knew, const float* __restrict__ vnew) {
    int bh    = blockIdx.x;
    int split = blockIdx.y;
    int b     = bh >> 4;
    int h     = bh & 15;
    int warp  = threadIdx.x >> 5;
    int lane  = threadIdx.x & 31;

    const float4* q4p = (const float4*)(g_q + b * D_ + h * HD_);
    float4 q4 = q4p[lane];  // q pre-scaled by SCALING

    size_t base = ((size_t)b * SPAST) * D_ + h * HD_;

    float  m = -1e30f, l = 0.f;
    float4 acc = make_float4(0.f, 0.f, 0.f, 0.f);

    int s0 = split * CHUNK + warp;
    int s_end = split * CHUNK + CHUNK;

#pragma unroll 4
    for (int s = s0; s < s_end; s += 8) {
        const float4* kr = (const float4*)(pk + base + (size_t)s * D_);
        const float4* vr = (const float4*)(pv + base + (size_t)s * D_);
        float4 k4 = __ldcs(&kr[lane]);
        float4 v4 = __ldcs(&vr[lane]);
        float sc = k4.x * q4.x + k4.y * q4.y + k4.z * q4.z + k4.w * q4.w;
        sc += __shfl_xor_sync(0xffffffffu, sc, 16);
        sc += __shfl_xor_sync(0xffffffffu, sc, 8);
        sc += __shfl_xor_sync(0xffffffffu, sc, 4);
        sc += __shfl_xor_sync(0xffffffffu, sc, 2);
        sc += __shfl_xor_sync(0xffffffffu, sc, 1);
        sc += mask[s];
        float nm   = fmaxf(m, sc);
        float corr = __expf(m - nm);
        float p    = __expf(sc - nm);
        m = nm;
        l = l * corr + p;
        acc.x = acc.x * corr + p * v4.x;
        acc.y = acc.y * corr + p * v4.y;
        acc.z = acc.z * corr + p * v4.z;
        acc.w = acc.w * corr + p * v4.w;
    }

    // The new token (s = 4096) lives in the last split, handled by warp 0.
    if (split == SPLITS - 1 && warp == 0) {
        const float4* kr = (const float4*)(knew + b * D_ + h * HD_);
        const float4* vr = (const float4*)(vnew + b * D_ + h * HD_);
        float4 k4 = kr[lane];
        float4 v4 = vr[lane];
        float sc = k4.x * q4.x + k4.y * q4.y + k4.z * q4.z + k4.w * q4.w;
        sc += __shfl_xor_sync(0xffffffffu, sc, 16);
        sc += __shfl_xor_sync(0xffffffffu, sc, 8);
        sc += __shfl_xor_sync(0xffffffffu, sc, 4);
        sc += __shfl_xor_sync(0xffffffffu, sc, 2);
        sc += __shfl_xor_sync(0xffffffffu, sc, 1);
        sc += mask[SPAST];
        float nm   = fmaxf(m, sc);
        float corr = __expf(m - nm);
        float p    = __expf(sc - nm);
        m = nm;
        l = l * corr + p;
        acc.x = acc.x * corr + p * v4.x;
        acc.y = acc.y * corr + p * v4.y;
        acc.z = acc.z * corr + p * v4.z;
        acc.w = acc.w * corr + p * v4.w;
    }

    // Combine the 8 warps of this block.
    __shared__ float  sm_m[8], sm_l[8];
    __shared__ float4 sm_acc[8][32];
    sm_acc[warp][lane] = acc;
    if (lane == 0) { sm_m[warp] = m; sm_l[warp] = l; }
    __syncthreads();

    int idx = bh * SPLITS + split;
    if (threadIdx.x < HD_) {
        int d = threadIdx.x;
        float M = -1e30f;
#pragma unroll
        for (int w = 0; w < 8; w++) M = fmaxf(M, sm_m[w]);
        float L = 0.f, A = 0.f;
        const float* accf = (const float*)sm_acc;
#pragma unroll
        for (int w = 0; w < 8; w++) {
            float e = __expf(sm_m[w] - M);
            L += sm_l[w] * e;
            A += accf[w * HD_ + d] * e;
        }
        g_pacc[idx * HD_ + d] = A;
        if (d == 0) { g_pm[idx] = M; g_pl[idx] = L; }
    }

    // ---- Fused split-combine: last block per bh does the reduction ----
    __threadfence();
    __shared__ bool is_last;
    __syncthreads();
    if (threadIdx.x == 0) {
        unsigned prev = atomicAdd(&g_cnt[bh], 1u);
        is_last = (prev == SPLITS - 1);
    }
    __syncthreads();
    if (!is_last) return;

    __threadfence();
    if (threadIdx.x < HD_) {
        int d = threadIdx.x;
        float M = -1e30f;
#pragma unroll
        for (int i = 0; i < SPLITS; i++)
            M = fmaxf(M, __ldcg(&g_pm[bh * SPLITS + i]));
        float L = 0.f, A = 0.f;
#pragma unroll
        for (int i = 0; i < SPLITS; i++) {
            float e = __expf(__ldcg(&g_pm[bh * SPLITS + i]) - M);
            L += __ldcg(&g_pl[bh * SPLITS + i]) * e;
            A += __ldcg(&g_pacc[(bh * SPLITS + i) * HD_ + d]) * e;
        }
        g_attn[b * D_ + h * HD_ + d] = A / L;
    }
    __syncthreads();
    if (threadIdx.x == 0) g_cnt[bh] = 0;   // reset for the next launch/replay
}

// ---------------------------------------------------------------------------
extern "C" void kernel_launch(void* const* d_in, const int* in_sizes, int n_in,
                              void* d_out, int out_size) {
    const float* hs   = (const float*)d_in[0];
    const float* pk   = (const float*)d_in[1];
    const float* pv   = (const float*)d_in[2];
    const float* mask = (const float*)d_in[3];
    const float* Wq   = (const float*)d_in[4];
    const float* bq   = (const float*)d_in[5];
    const float* Wk   = (const float*)d_in[6];
    const float* bk   = (const float*)d_in[7];
    const float* Wv   = (const float*)d_in[8];
    const float* bv   = (const float*)d_in[9];
    const float* Wo   = (const float*)d_in[10];
    const float* bo   = (const float*)d_in[11];

    float* out  = (float*)d_out;          // [0, 32768): attn_output
    float* knew = out + B_ * D_;          // [32768, 65536): new_key
    float* vnew = out + 2 * B_ * D_;      // [65536, 98304): new_value

    float* qptr;  cudaGetSymbolAddress((void**)&qptr, g_q);
    float* aptr;  cudaGetSymbolAddress((void**)&aptr, g_attn);

    // 1. Seed all gemv destinations with their biases (one kernel).
    init_kernel<<<128, 256>>>(qptr, knew, vnew, out, bq, bk, bv, bo);

    // 2. Fused split-K QKV projection (768 blocks, 2 blocks/SM resident).
    GemvArgs a;
    a.W[0] = Wq; a.out[0] = qptr; a.scale[0] = SCALING;
    a.W[1] = Wk; a.out[1] = knew; a.scale[1] = 1.f;
    a.W[2] = Wv; a.out[2] = vnew; a.scale[2] = 1.f;
    gemv_kernel<4><<<dim3(192, 4), 256>>>(hs, a);

    // 3. Split-S attention partials + fused combine (HBM-bound 1.07 GB).
    attn_partial_kernel<<<dim3(B_ * H_, SPLITS), 256>>>(pk, pv, mask, knew, vnew);

    // 4. Output projection (split-K=4 -> 256 blocks over 2048 rows).
    GemvArgs ao;
    ao.W[0] = Wo; ao.out[0] = out; ao.scale[0] = 1.f;
    ao.W[1] = Wo; ao.out[1] = out; ao.scale[1] = 1.f;
    ao.W[2] = Wo; ao.out[2] = out; ao.scale[2] = 1.f;
    gemv_kernel<4><<<dim3(64, 4), 256>>>(aptr, ao);
}

// round 5
// speedup vs baseline: 1.1106x; 1.1106x over previous
#include <cuda_runtime.h>
#include <math.h>

// Problem constants
constexpr int B_   = 16;
constexpr int H_   = 16;
constexpr int HD_  = 128;
constexpr int D_   = 2048;
constexpr int SPAST = 4096;
constexpr int SPLITS = 8;
constexpr int CHUNK  = 512;   // SPAST / SPLITS
constexpr float SCALING = 0.08838834764831845f;  // 128^-0.5

// Scratch (static device globals — no allocation allowed)
__device__ float g_q[B_ * D_];
__device__ float g_attn[B_ * D_];
__device__ float g_pm[B_ * H_ * SPLITS];
__device__ float g_pl[B_ * H_ * SPLITS];
__device__ float g_pacc[B_ * H_ * SPLITS * HD_];

struct GemvArgs {
    const float* W[3];
    float*       out[3];
    float        scale[3];
};

// ---------------------------------------------------------------------------
// Single init: seed q/knew/vnew/out with their biases so the split-K gemvs
// can pure-atomicAdd afterwards.
// ---------------------------------------------------------------------------
__global__ __launch_bounds__(256) void init_kernel(
    float* q, float* knew, float* vnew, float* out,
    const float* __restrict__ bq, const float* __restrict__ bk,
    const float* __restrict__ bv, const float* __restrict__ bo) {
    int idx = blockIdx.x * 256 + threadIdx.x;   // [0, 32768)
    int o = idx & (D_ - 1);
    q[idx]    = bq[o] * SCALING;
    knew[idx] = bk[o];
    vnew[idx] = bv[o];
    out[idx]  = bo[o];
}

// ---------------------------------------------------------------------------
// Split-K GEMV: out[b, o] += scale * sum_{d in chunk} x[b,d] * W[o,d]
// 128-thread blocks (3 blocks/SM at ~141 regs -> 12 warps/SM instead of 8).
// Each warp owns 4 consecutive output rows, register-blocks all 16 batches.
// Weight loads are software-pipelined (next iter prefetched before the FMA
// block) so 8 weight float4-loads stay in flight per warp.
// ---------------------------------------------------------------------------
template <int KSPLIT>
__global__ __launch_bounds__(128) void gemv_kernel(const float* __restrict__ x,
                                                   GemvArgs a) {
    int gw   = (blockIdx.x * 128 + threadIdx.x) >> 5;  // global warp id
    int lane = threadIdx.x & 31;
    int row0 = gw * 4;
    int mi   = row0 >> 11;      // which matrix (rows are 2048 per matrix)
    int o0   = row0 & 2047;

    const float4* W = (const float4*)a.W[mi];
    const float4* X = (const float4*)x;

    float acc[4][16];
#pragma unroll
    for (int r = 0; r < 4; r++)
#pragma unroll
        for (int b = 0; b < 16; b++) acc[r][b] = 0.f;

    constexpr int ITERS = 16 / KSPLIT;
    int i0 = blockIdx.y * ITERS;

    // Prefetch iteration 0 weights.
    int d4 = i0 * 32 + lane;
    float4 w0 = __ldcs(&W[(size_t)(o0 + 0) * 512 + d4]);
    float4 w1 = __ldcs(&W[(size_t)(o0 + 1) * 512 + d4]);
    float4 w2 = __ldcs(&W[(size_t)(o0 + 2) * 512 + d4]);
    float4 w3 = __ldcs(&W[(size_t)(o0 + 3) * 512 + d4]);

#pragma unroll
    for (int ii = 0; ii < ITERS; ii++) {
        float4 c0 = w0, c1 = w1, c2 = w2, c3 = w3;
        int dcur = d4;
        if (ii + 1 < ITERS) {
            d4 += 32;
            w0 = __ldcs(&W[(size_t)(o0 + 0) * 512 + d4]);
            w1 = __ldcs(&W[(size_t)(o0 + 1) * 512 + d4]);
            w2 = __ldcs(&W[(size_t)(o0 + 2) * 512 + d4]);
            w3 = __ldcs(&W[(size_t)(o0 + 3) * 512 + d4]);
        }
#pragma unroll
        for (int b = 0; b < 16; b++) {
            float4 xv = X[b * 512 + dcur];
            acc[0][b] += c0.x * xv.x + c0.y * xv.y + c0.z * xv.z + c0.w * xv.w;
            acc[1][b] += c1.x * xv.x + c1.y * xv.y + c1.z * xv.z + c1.w * xv.w;
            acc[2][b] += c2.x * xv.x + c2.y * xv.y + c2.z * xv.z + c2.w * xv.w;
            acc[3][b] += c3.x * xv.x + c3.y * xv.y + c3.z * xv.z + c3.w * xv.w;
        }
    }

    // Warp-reduce each of the 64 partial sums
#pragma unroll
    for (int r = 0; r < 4; r++)
#pragma unroll
        for (int b = 0; b < 16; b++) {
            float v = acc[r][b];
            v += __shfl_xor_sync(0xffffffffu, v, 16);
            v += __shfl_xor_sync(0xffffffffu, v, 8);
            v += __shfl_xor_sync(0xffffffffu, v, 4);
            v += __shfl_xor_sync(0xffffffffu, v, 2);
            v += __shfl_xor_sync(0xffffffffu, v, 1);
            acc[r][b] = v;
        }

    float* out = a.out[mi];
    float  sc  = a.scale[mi];
#pragma unroll
    for (int r = 0; r < 4; r++)
#pragma unroll
        for (int b = 0; b < 16; b++)
            if (lane == b)
                atomicAdd(&out[b * D_ + o0 + r], acc[r][b] * sc);
}

// ---------------------------------------------------------------------------
// Split-S flash-decode attention partials (round-3 proven structure).
// grid = (256 bh, 8 splits), block = 256 (8 warps). Warp-per-row online
// softmax; each lane owns 4 contiguous head-dim elements (float4).
// K/V are a 1 GB single-use stream: __ldcs keeps them out of L2's way.
// ---------------------------------------------------------------------------
__global__ __launch_bounds__(256) void attn_partial_kernel(
    const float* __restrict__ pk, const float* __restrict__ pv,
    const float* __restrict__ mask,
    const float* __restrict__ knew, const float* __restrict__ vnew) {
    int bh    = blockIdx.x;
    int split = blockIdx.y;
    int b     = bh >> 4;
    int h     = bh & 15;
    int warp  = threadIdx.x >> 5;
    int lane  = threadIdx.x & 31;

    const float4* q4p = (const float4*)(g_q + b * D_ + h * HD_);
    float4 q4 = q4p[lane];  // q pre-scaled by SCALING

    size_t base = ((size_t)b * SPAST) * D_ + h * HD_;

    float  m = -1e30f, l = 0.f;
    float4 acc = make_float4(0.f, 0.f, 0.f, 0.f);

    int s0 = split * CHUNK + warp;
    int s_end = split * CHUNK + CHUNK;

#pragma unroll 4
    for (int s = s0; s < s_end; s += 8) {
        const float4* kr = (const float4*)(pk + base + (size_t)s * D_);
        const float4* vr = (const float4*)(pv + base + (size_t)s * D_);
        float4 k4 = __ldcs(&kr[lane]);
        float4 v4 = __ldcs(&vr[lane]);
        float sc = k4.x * q4.x + k4.y * q4.y + k4.z * q4.z + k4.w * q4.w;
        sc += __shfl_xor_sync(0xffffffffu, sc, 16);
        sc += __shfl_xor_sync(0xffffffffu, sc, 8);
        sc += __shfl_xor_sync(0xffffffffu, sc, 4);
        sc += __shfl_xor_sync(0xffffffffu, sc, 2);
        sc += __shfl_xor_sync(0xffffffffu, sc, 1);
        sc += mask[s];
        float nm   = fmaxf(m, sc);
        float corr = __expf(m - nm);
        float p    = __expf(sc - nm);
        m = nm;
        l = l * corr + p;
        acc.x = acc.x * corr + p * v4.x;
        acc.y = acc.y * corr + p * v4.y;
        acc.z = acc.z * corr + p * v4.z;
        acc.w = acc.w * corr + p * v4.w;
    }

    // The new token (s = 4096) lives in the last split, handled by warp 0.
    if (split == SPLITS - 1 && warp == 0) {
        const float4* kr = (const float4*)(knew + b * D_ + h * HD_);
        const float4* vr = (const float4*)(vnew + b * D_ + h * HD_);
        float4 k4 = kr[lane];
        float4 v4 = vr[lane];
        float sc = k4.x * q4.x + k4.y * q4.y + k4.z * q4.z + k4.w * q4.w;
        sc += __shfl_xor_sync(0xffffffffu, sc, 16);
        sc += __shfl_xor_sync(0xffffffffu, sc, 8);
        sc += __shfl_xor_sync(0xffffffffu, sc, 4);
        sc += __shfl_xor_sync(0xffffffffu, sc, 2);
        sc += __shfl_xor_sync(0xffffffffu, sc, 1);
        sc += mask[SPAST];
        float nm   = fmaxf(m, sc);
        float corr = __expf(m - nm);
        float p    = __expf(sc - nm);
        m = nm;
        l = l * corr + p;
        acc.x = acc.x * corr + p * v4.x;
        acc.y = acc.y * corr + p * v4.y;
        acc.z = acc.z * corr + p * v4.z;
        acc.w = acc.w * corr + p * v4.w;
    }

    // Combine the 8 warps of this block.
    __shared__ float  sm_m[8], sm_l[8];
    __shared__ float4 sm_acc[8][32];
    sm_acc[warp][lane] = acc;
    if (lane == 0) { sm_m[warp] = m; sm_l[warp] = l; }
    __syncthreads();

    if (threadIdx.x < HD_) {
        int d = threadIdx.x;
        float M = -1e30f;
#pragma unroll
        for (int w = 0; w < 8; w++) M = fmaxf(M, sm_m[w]);
        float L = 0.f, A = 0.f;
        const float* accf = (const float*)sm_acc;
#pragma unroll
        for (int w = 0; w < 8; w++) {
            float e = __expf(sm_m[w] - M);
            L += sm_l[w] * e;
            A += accf[w * HD_ + d] * e;
        }
        int idx = bh * SPLITS + split;
        g_pacc[idx * HD_ + d] = A;
        if (d == 0) { g_pm[idx] = M; g_pl[idx] = L; }
    }
}

// ---------------------------------------------------------------------------
// Combine the 8 split partials per (b,h) into the attention output vector.
// ---------------------------------------------------------------------------
__global__ __launch_bounds__(128) void attn_combine_kernel() {
    int bh = blockIdx.x;
    int d  = threadIdx.x;
    float M = -1e30f;
#pragma unroll
    for (int i = 0; i < SPLITS; i++) M = fmaxf(M, g_pm[bh * SPLITS + i]);
    float L = 0.f, A = 0.f;
#pragma unroll
    for (int i = 0; i < SPLITS; i++) {
        float e = __expf(g_pm[bh * SPLITS + i] - M);
        L += g_pl[bh * SPLITS + i] * e;
        A += g_pacc[(bh * SPLITS + i) * HD_ + d] * e;
    }
    int b = bh >> 4, h = bh & 15;
    g_attn[b * D_ + h * HD_ + d] = A / L;
}

// ---------------------------------------------------------------------------
extern "C" void kernel_launch(void* const* d_in, const int* in_sizes, int n_in,
                              void* d_out, int out_size) {
    const float* hs   = (const float*)d_in[0];
    const float* pk   = (const float*)d_in[1];
    const float* pv   = (const float*)d_in[2];
    const float* mask = (const float*)d_in[3];
    const float* Wq   = (const float*)d_in[4];
    const float* bq   = (const float*)d_in[5];
    const float* Wk   = (const float*)d_in[6];
    const float* bk   = (const float*)d_in[7];
    const float* Wv   = (const float*)d_in[8];
    const float* bv   = (const float*)d_in[9];
    const float* Wo   = (const float*)d_in[10];
    const float* bo   = (const float*)d_in[11];

    float* out  = (float*)d_out;          // [0, 32768): attn_output
    float* knew = out + B_ * D_;          // [32768, 65536): new_key
    float* vnew = out + 2 * B_ * D_;      // [65536, 98304): new_value

    float* qptr;  cudaGetSymbolAddress((void**)&qptr, g_q);
    float* aptr;  cudaGetSymbolAddress((void**)&aptr, g_attn);

    // 1. Seed all gemv destinations with their biases (one kernel).
    init_kernel<<<128, 256>>>(qptr, knew, vnew, out, bq, bk, bv, bo);

    // 2. Fused split-K QKV projection. 128-thd blocks: 6144 rows / 16 rows
    //    per block = 384 blocks in x, KSPLIT=2 -> 768 blocks total.
    GemvArgs a;
    a.W[0] = Wq; a.out[0] = qptr; a.scale[0] = SCALING;
    a.W[1] = Wk; a.out[1] = knew; a.scale[1] = 1.f;
    a.W[2] = Wv; a.out[2] = vnew; a.scale[2] = 1.f;
    gemv_kernel<2><<<dim3(384, 2), 128>>>(hs, a);

    // 3. Split-S attention partials (the HBM-bound 1.07 GB stream).
    attn_partial_kernel<<<dim3(B_ * H_, SPLITS), 256>>>(pk, pv, mask, knew, vnew);

    // 4. Combine partials.
    attn_combine_kernel<<<B_ * H_, 128>>>();

    // 5. Output projection: 2048 rows / 16 = 128 blocks in x, KSPLIT=4.
    GemvArgs ao;
    ao.W[0] = Wo; ao.out[0] = out; ao.scale[0] = 1.f;
    ao.W[1] = Wo; ao.out[1] = out; ao.scale[1] = 1.f;
    ao.W[2] = Wo; ao.out[2] = out; ao.scale[2] = 1.f;
    gemv_kernel<4><<<dim3(128, 4), 128>>>(aptr, ao);
}